// round 1
// baseline (speedup 1.0000x reference)
#include <cuda_runtime.h>
#include <cuda_bf16.h>
#include <cstdint>
#include <cstddef>

// ---------------------------------------------------------------------------
// Problem constants
//   x  : [8*2048, 1024] fp32
//   Wq/Wk/Wv : [1024, 1024] fp32 (torch Linear weight, out = x @ W^T + b)
//   out: [8, 2048, 1024] fp32 = softmax(Q K^T / 32) V   per batch
// ---------------------------------------------------------------------------

#define BT_TOK   16384          // 8*2048 tokens
#define DMODEL   1024
#define TSEQ     2048
#define NBATCH   8
#define SCALE    0.03125f

// Scratch (static device globals; dynamic allocation is forbidden)
__device__ float g_q[(size_t)BT_TOK * DMODEL];           // 64 MB
__device__ float g_k[(size_t)BT_TOK * DMODEL];           // 64 MB
__device__ float g_v[(size_t)BT_TOK * DMODEL];           // 64 MB
__device__ float g_s[(size_t)NBATCH * TSEQ * TSEQ];      // 128 MB

__device__ __forceinline__ unsigned f2tf32(float f) {
    unsigned u;
    asm("cvt.rna.tf32.f32 %0, %1;" : "=r"(u) : "f"(f));
    return u;
}

__device__ __forceinline__ void mma_tf32(float c[4], const unsigned a[4], const unsigned b[2]) {
    asm volatile(
        "mma.sync.aligned.m16n8k8.row.col.f32.tf32.tf32.f32 "
        "{%0,%1,%2,%3}, {%4,%5,%6,%7}, {%8,%9}, {%0,%1,%2,%3};"
        : "+f"(c[0]), "+f"(c[1]), "+f"(c[2]), "+f"(c[3])
        : "r"(a[0]), "r"(a[1]), "r"(a[2]), "r"(a[3]), "r"(b[0]), "r"(b[1]));
}

// ---------------------------------------------------------------------------
// Tiled tf32 GEMM.
//   B_TRANS = true : C[M,N] = alpha * A[M,K] * B[N,K]^T (+ bias)   ("NT")
//   B_TRANS = false: C[M,N] = alpha * A[M,K] * B[K,N]   (+ bias)   ("NN")
// CTA tile 128x128x32, 8 warps (4 x 2), warp tile 32x64, m16n8k8.
// All dims assumed multiples of 128 (true for this problem) -> no predication.
// blockIdx.z = batch, strides sA/sB/sC in elements.
// ---------------------------------------------------------------------------
template <bool B_TRANS>
__global__ void __launch_bounds__(256, 2)
gemm_tf32(const float* __restrict__ A, int lda, size_t sA,
          const float* __restrict__ B, int ldb, size_t sB,
          float* __restrict__ C, int ldc, size_t sC,
          const float* __restrict__ bias, float alpha, int K)
{
    __shared__ unsigned As[128 * 36];                       // [m][k], pad 36
    __shared__ unsigned Bs[B_TRANS ? 128 * 36 : 32 * 132];  // NT: [n][k]p36, NN: [k][n]p132

    A += blockIdx.z * sA;
    B += blockIdx.z * sB;
    C += blockIdx.z * sC;

    const int m0 = blockIdx.y * 128;
    const int n0 = blockIdx.x * 128;
    const int tid  = threadIdx.x;
    const int lane = tid & 31;
    const int warp = tid >> 5;
    const int wm = (warp & 3) * 32;   // warp row offset inside CTA tile
    const int wn = (warp >> 2) * 64;  // warp col offset inside CTA tile

    float acc[2][8][4];
#pragma unroll
    for (int mt = 0; mt < 2; mt++)
#pragma unroll
        for (int nt = 0; nt < 8; nt++)
#pragma unroll
            for (int i = 0; i < 4; i++) acc[mt][nt][i] = 0.0f;

    for (int k0 = 0; k0 < K; k0 += 32) {
        __syncthreads();
        // ---- load A tile [128 x 32], convert to tf32 in-flight ----
#pragma unroll
        for (int i = 0; i < 4; i++) {
            int idx = tid + i * 256;
            int r = idx >> 3;
            int c = (idx & 7) * 4;
            const float4 vv = *(const float4*)(A + (size_t)(m0 + r) * lda + k0 + c);
            uint4 t = make_uint4(f2tf32(vv.x), f2tf32(vv.y), f2tf32(vv.z), f2tf32(vv.w));
            *(uint4*)&As[r * 36 + c] = t;
        }
        // ---- load B tile ----
        if (B_TRANS) {
#pragma unroll
            for (int i = 0; i < 4; i++) {
                int idx = tid + i * 256;
                int r = idx >> 3;
                int c = (idx & 7) * 4;
                const float4 vv = *(const float4*)(B + (size_t)(n0 + r) * ldb + k0 + c);
                uint4 t = make_uint4(f2tf32(vv.x), f2tf32(vv.y), f2tf32(vv.z), f2tf32(vv.w));
                *(uint4*)&Bs[r * 36 + c] = t;
            }
        } else {
#pragma unroll
            for (int i = 0; i < 4; i++) {
                int idx = tid + i * 256;
                int r = idx >> 5;            // k row (0..31)
                int c = (idx & 31) * 4;      // n col
                const float4 vv = *(const float4*)(B + (size_t)(k0 + r) * ldb + n0 + c);
                uint4 t = make_uint4(f2tf32(vv.x), f2tf32(vv.y), f2tf32(vv.z), f2tf32(vv.w));
                *(uint4*)&Bs[r * 132 + c] = t;
            }
        }
        __syncthreads();

        // ---- 4 k-steps of 8 ----
#pragma unroll
        for (int ks = 0; ks < 4; ks++) {
            const int kk = ks * 8;
            unsigned a[2][4];
#pragma unroll
            for (int mt = 0; mt < 2; mt++) {
                int r = wm + mt * 16 + (lane >> 2);
                int c = kk + (lane & 3);
                a[mt][0] = As[r * 36 + c];
                a[mt][1] = As[(r + 8) * 36 + c];
                a[mt][2] = As[r * 36 + c + 4];
                a[mt][3] = As[(r + 8) * 36 + c + 4];
            }
            unsigned b[8][2];
#pragma unroll
            for (int nt = 0; nt < 8; nt++) {
                int n = wn + nt * 8 + (lane >> 2);
                if (B_TRANS) {
                    b[nt][0] = Bs[n * 36 + kk + (lane & 3)];
                    b[nt][1] = Bs[n * 36 + kk + (lane & 3) + 4];
                } else {
                    b[nt][0] = Bs[(kk + (lane & 3)) * 132 + n];
                    b[nt][1] = Bs[(kk + (lane & 3) + 4) * 132 + n];
                }
            }
#pragma unroll
            for (int mt = 0; mt < 2; mt++)
#pragma unroll
                for (int nt = 0; nt < 8; nt++) mma_tf32(acc[mt][nt], a[mt], b[nt]);
        }
    }

    // ---- epilogue: C = alpha * acc (+ bias) ----
#pragma unroll
    for (int nt = 0; nt < 8; nt++) {
        int c = n0 + wn + nt * 8 + (lane & 3) * 2;
        float2 bb = make_float2(0.0f, 0.0f);
        if (bias) bb = *(const float2*)(bias + c);
#pragma unroll
        for (int mt = 0; mt < 2; mt++) {
            int r = m0 + wm + mt * 16 + (lane >> 2);
            float2 o0 = make_float2(acc[mt][nt][0] * alpha + bb.x,
                                    acc[mt][nt][1] * alpha + bb.y);
            float2 o1 = make_float2(acc[mt][nt][2] * alpha + bb.x,
                                    acc[mt][nt][3] * alpha + bb.y);
            *(float2*)(C + (size_t)r * ldc + c)       = o0;
            *(float2*)(C + (size_t)(r + 8) * ldc + c) = o1;
        }
    }
}

// ---------------------------------------------------------------------------
// Row softmax over rows of length 2048, in place. One CTA (256 thr) per row.
// ---------------------------------------------------------------------------
__global__ void __launch_bounds__(256)
softmax2048(float* __restrict__ S)
{
    const int row = blockIdx.x;
    float* p = S + (size_t)row * 2048;
    const int t = threadIdx.x;

    float v[8];
#pragma unroll
    for (int i = 0; i < 8; i++) v[i] = p[t + i * 256];

    float m = v[0];
#pragma unroll
    for (int i = 1; i < 8; i++) m = fmaxf(m, v[i]);
#pragma unroll
    for (int o = 16; o; o >>= 1) m = fmaxf(m, __shfl_xor_sync(0xffffffffu, m, o));

    __shared__ float red[8];
    if ((t & 31) == 0) red[t >> 5] = m;
    __syncthreads();
#pragma unroll
    for (int i = 0; i < 8; i++) m = fmaxf(m, red[i]);

    float s = 0.0f;
#pragma unroll
    for (int i = 0; i < 8; i++) { v[i] = __expf(v[i] - m); s += v[i]; }
#pragma unroll
    for (int o = 16; o; o >>= 1) s += __shfl_xor_sync(0xffffffffu, s, o);

    __syncthreads();
    if ((t & 31) == 0) red[t >> 5] = s;
    __syncthreads();
    s = 0.0f;
#pragma unroll
    for (int i = 0; i < 8; i++) s += red[i];

    const float inv = 1.0f / s;
#pragma unroll
    for (int i = 0; i < 8; i++) p[t + i * 256] = v[i] * inv;
}

// ---------------------------------------------------------------------------
// Launch pipeline (graph-capturable: kernels only)
// ---------------------------------------------------------------------------
extern "C" void kernel_launch(void* const* d_in, const int* in_sizes, int n_in,
                              void* d_out, int out_size)
{
    (void)in_sizes; (void)n_in; (void)out_size;
    const float* x  = (const float*)d_in[0];
    const float* Wq = (const float*)d_in[1];
    const float* bq = (const float*)d_in[2];
    const float* Wk = (const float*)d_in[3];
    const float* bk = (const float*)d_in[4];
    const float* Wv = (const float*)d_in[5];
    const float* bv = (const float*)d_in[6];
    float* out = (float*)d_out;

    float *q, *k, *v, *s;
    cudaGetSymbolAddress((void**)&q, g_q);
    cudaGetSymbolAddress((void**)&k, g_k);
    cudaGetSymbolAddress((void**)&v, g_v);
    cudaGetSymbolAddress((void**)&s, g_s);

    const dim3 blk(256);

    // 1) Q/K/V projections: [16384,1024] x [1024,1024]^T + bias
    const dim3 g1(DMODEL / 128, BT_TOK / 128, 1);
    gemm_tf32<true><<<g1, blk>>>(x, DMODEL, 0, Wq, DMODEL, 0, q, DMODEL, 0, bq, 1.0f, DMODEL);
    gemm_tf32<true><<<g1, blk>>>(x, DMODEL, 0, Wk, DMODEL, 0, k, DMODEL, 0, bk, 1.0f, DMODEL);
    gemm_tf32<true><<<g1, blk>>>(x, DMODEL, 0, Wv, DMODEL, 0, v, DMODEL, 0, bv, 1.0f, DMODEL);

    // 2) S = Q K^T * scale, per batch
    const size_t sQKV = (size_t)TSEQ * DMODEL;
    const size_t sS   = (size_t)TSEQ * TSEQ;
    const dim3 g2(TSEQ / 128, TSEQ / 128, NBATCH);
    gemm_tf32<true><<<g2, blk>>>(q, DMODEL, sQKV, k, DMODEL, sQKV,
                                 s, TSEQ, sS, nullptr, SCALE, DMODEL);

    // 3) row softmax, in place
    softmax2048<<<NBATCH * TSEQ, blk>>>(s);

    // 4) O = P V, per batch
    const dim3 g3(DMODEL / 128, TSEQ / 128, NBATCH);
    gemm_tf32<false><<<g3, blk>>>(s, TSEQ, sS, v, DMODEL, sQKV,
                                  out, DMODEL, sQKV, nullptr, 1.0f, DMODEL * 2);
}

// round 3
// speedup vs baseline: 1.2776x; 1.2776x over previous
#include <cuda_runtime.h>
#include <cuda_bf16.h>
#include <cstdint>
#include <cstddef>

// ---------------------------------------------------------------------------
// softmax(QK^T/32)V with Q/K/V = x W^T + b.
//   x  : [8*2048, 1024] fp32,  W* : [1024,1024] fp32, out: [8,2048,1024] fp32
// tf32 mma.sync pipeline, cp.async double-buffered, 64x64 warp tiles.
// All mma operands are pre-rounded to tf32 (rna) in memory so the HW
// truncation inside mma is exact.
// ---------------------------------------------------------------------------

#define BT_TOK   16384
#define DMODEL   1024
#define TSEQ     2048
#define NBATCH   8
#define SCALE    0.03125f

// Scratch (device globals; allocation is forbidden)
__device__ float g_q[(size_t)BT_TOK * DMODEL];           // 64 MB
__device__ float g_k[(size_t)BT_TOK * DMODEL];           // 64 MB
__device__ float g_v[(size_t)BT_TOK * DMODEL];           // 64 MB
__device__ float g_s[(size_t)NBATCH * TSEQ * TSEQ];      // 128 MB
__device__ float g_x[(size_t)BT_TOK * DMODEL];           // 64 MB (tf32-rounded x)
__device__ float g_w[3][(size_t)DMODEL * DMODEL];        // 12 MB (tf32-rounded W)

__device__ __forceinline__ float tf32r(float f) {
    unsigned u;
    asm("cvt.rna.tf32.f32 %0, %1;" : "=r"(u) : "f"(f));
    return __uint_as_float(u);
}

__device__ __forceinline__ void mma_tf32(float c[4], const unsigned a[4], const unsigned b[2]) {
    asm volatile(
        "mma.sync.aligned.m16n8k8.row.col.f32.tf32.tf32.f32 "
        "{%0,%1,%2,%3}, {%4,%5,%6,%7}, {%8,%9}, {%0,%1,%2,%3};"
        : "+f"(c[0]), "+f"(c[1]), "+f"(c[2]), "+f"(c[3])
        : "r"(a[0]), "r"(a[1]), "r"(a[2]), "r"(a[3]), "r"(b[0]), "r"(b[1]));
}

__device__ __forceinline__ void cp_async16(void* smem, const void* g) {
    unsigned s = (unsigned)__cvta_generic_to_shared(smem);
    asm volatile("cp.async.cg.shared.global [%0], [%1], 16;" :: "r"(s), "l"(g));
}
__device__ __forceinline__ void cp_commit() { asm volatile("cp.async.commit_group;"); }
template <int N>
__device__ __forceinline__ void cp_wait() { asm volatile("cp.async.wait_group %0;" :: "n"(N)); }

// ---------------------------------------------------------------------------
// tf32 GEMM, CTA tile 128x128x32, 128 threads (4 warps, 2x2), warp tile 64x64.
//   B_TRANS=true : C = alpha*A[M,K]*B[N,K]^T (+bias)
//   B_TRANS=false: C = alpha*A[M,K]*B[K,N]   (+bias)
// Double-buffered cp.async. M,N multiples of 128; K multiple of 32.
// round_out!=0: epilogue values rounded to tf32 (producer-side rounding).
// ---------------------------------------------------------------------------
template <bool B_TRANS>
__global__ void __launch_bounds__(128, 2)
gemm_tf32(const float* __restrict__ A, int lda, size_t sA,
          const float* __restrict__ B, int ldb, size_t sB,
          float* __restrict__ C, int ldc, size_t sC,
          const float* __restrict__ bias, float alpha, int K, int round_out)
{
    constexpr int AST = 36;                       // A smem stride (floats)
    constexpr int BST = B_TRANS ? 36 : 136;       // B smem stride
    constexpr int ASZ = 128 * AST;                // per-buffer sizes
    constexpr int BSZ = B_TRANS ? 128 * 36 : 32 * 136;

    extern __shared__ unsigned sh[];
    unsigned* As = sh;             // [2][ASZ]
    unsigned* Bs = sh + 2 * ASZ;   // [2][BSZ]

    A += blockIdx.z * sA;
    B += blockIdx.z * sB;
    C += blockIdx.z * sC;

    const int m0 = blockIdx.y * 128;
    const int n0 = blockIdx.x * 128;
    const int tid = threadIdx.x;
    const int lane = tid & 31;
    const int warp = tid >> 5;
    const int wm = (warp & 1) * 64;
    const int wn = (warp >> 1) * 64;

    // staging coords (8 cp.async each for A and B per stage)
    const int ar0 = tid >> 3, ac = (tid & 7) * 4;       // A & NT-B: [128 x 32]
    const int br0 = tid >> 5, bc = (tid & 31) * 4;      // NN-B: [32 x 128]

    float acc[4][8][4] = {};

    auto load_stage = [&](int buf, int k0) {
        {
            const float* src = A + (size_t)(m0 + ar0) * lda + k0 + ac;
            unsigned* dst = As + buf * ASZ + ar0 * AST + ac;
#pragma unroll
            for (int t = 0; t < 8; t++)
                cp_async16(dst + t * 16 * AST, src + (size_t)t * 16 * lda);
        }
        if (B_TRANS) {
            const float* src = B + (size_t)(n0 + ar0) * ldb + k0 + ac;
            unsigned* dst = Bs + buf * BSZ + ar0 * BST + ac;
#pragma unroll
            for (int t = 0; t < 8; t++)
                cp_async16(dst + t * 16 * BST, src + (size_t)t * 16 * ldb);
        } else {
            const float* src = B + (size_t)(k0 + br0) * ldb + n0 + bc;
            unsigned* dst = Bs + buf * BSZ + br0 * BST + bc;
#pragma unroll
            for (int t = 0; t < 8; t++)
                cp_async16(dst + t * 4 * BST, src + (size_t)t * 4 * ldb);
        }
    };

    const int NK = K >> 5;
    load_stage(0, 0);
    cp_commit();

    for (int i = 0; i < NK; i++) {
        const int buf = i & 1;
        if (i + 1 < NK) {
            load_stage(buf ^ 1, (i + 1) * 32);
            cp_commit();
            cp_wait<1>();
        } else {
            cp_wait<0>();
        }
        __syncthreads();

        const unsigned* Ab = As + buf * ASZ;
        const unsigned* Bb = Bs + buf * BSZ;

#pragma unroll
        for (int ks = 0; ks < 4; ks++) {
            const int kk = ks * 8;
            unsigned a[4][4];
#pragma unroll
            for (int mt = 0; mt < 4; mt++) {
                int r = wm + mt * 16 + (lane >> 2);
                int c = kk + (lane & 3);
                a[mt][0] = Ab[r * AST + c];
                a[mt][1] = Ab[(r + 8) * AST + c];
                a[mt][2] = Ab[r * AST + c + 4];
                a[mt][3] = Ab[(r + 8) * AST + c + 4];
            }
            unsigned b[8][2];
#pragma unroll
            for (int nt = 0; nt < 8; nt++) {
                int n = wn + nt * 8 + (lane >> 2);
                if (B_TRANS) {
                    b[nt][0] = Bb[n * BST + kk + (lane & 3)];
                    b[nt][1] = Bb[n * BST + kk + (lane & 3) + 4];
                } else {
                    b[nt][0] = Bb[(kk + (lane & 3)) * BST + n];
                    b[nt][1] = Bb[(kk + (lane & 3) + 4) * BST + n];
                }
            }
#pragma unroll
            for (int mt = 0; mt < 4; mt++)
#pragma unroll
                for (int nt = 0; nt < 8; nt++) mma_tf32(acc[mt][nt], a[mt], b[nt]);
        }
        __syncthreads();
    }

    // ---- epilogue ----
#pragma unroll
    for (int nt = 0; nt < 8; nt++) {
        int c = n0 + wn + nt * 8 + (lane & 3) * 2;
        float2 bb = make_float2(0.0f, 0.0f);
        if (bias) bb = *(const float2*)(bias + c);
#pragma unroll
        for (int mt = 0; mt < 4; mt++) {
            int r = m0 + wm + mt * 16 + (lane >> 2);
            float2 o0 = make_float2(acc[mt][nt][0] * alpha + bb.x,
                                    acc[mt][nt][1] * alpha + bb.y);
            float2 o1 = make_float2(acc[mt][nt][2] * alpha + bb.x,
                                    acc[mt][nt][3] * alpha + bb.y);
            if (round_out) {
                o0.x = tf32r(o0.x); o0.y = tf32r(o0.y);
                o1.x = tf32r(o1.x); o1.y = tf32r(o1.y);
            }
            *(float2*)(C + (size_t)r * ldc + c)       = o0;
            *(float2*)(C + (size_t)(r + 8) * ldc + c) = o1;
        }
    }
}

// ---------------------------------------------------------------------------
// Elementwise rna round to tf32, float4-vectorized.
// ---------------------------------------------------------------------------
__global__ void __launch_bounds__(256)
round_tf32_kernel(const float4* __restrict__ in, float4* __restrict__ out, int n4)
{
    int i = blockIdx.x * blockDim.x + threadIdx.x;
    if (i < n4) {
        float4 v = in[i];
        v.x = tf32r(v.x); v.y = tf32r(v.y); v.z = tf32r(v.z); v.w = tf32r(v.w);
        out[i] = v;
    }
}

// ---------------------------------------------------------------------------
// Row softmax over 2048-wide rows, in place; writes tf32-rounded probs.
// ---------------------------------------------------------------------------
__global__ void __launch_bounds__(256)
softmax2048(float* __restrict__ S)
{
    const int row = blockIdx.x;
    float* p = S + (size_t)row * 2048;
    const int t = threadIdx.x;

    float v[8];
#pragma unroll
    for (int i = 0; i < 8; i++) v[i] = p[t + i * 256];

    float m = v[0];
#pragma unroll
    for (int i = 1; i < 8; i++) m = fmaxf(m, v[i]);
#pragma unroll
    for (int o = 16; o; o >>= 1) m = fmaxf(m, __shfl_xor_sync(0xffffffffu, m, o));

    __shared__ float red[8];
    if ((t & 31) == 0) red[t >> 5] = m;
    __syncthreads();
#pragma unroll
    for (int i = 0; i < 8; i++) m = fmaxf(m, red[i]);

    float s = 0.0f;
#pragma unroll
    for (int i = 0; i < 8; i++) { v[i] = __expf(v[i] - m); s += v[i]; }
#pragma unroll
    for (int o = 16; o; o >>= 1) s += __shfl_xor_sync(0xffffffffu, s, o);

    __syncthreads();
    if ((t & 31) == 0) red[t >> 5] = s;
    __syncthreads();
    s = 0.0f;
#pragma unroll
    for (int i = 0; i < 8; i++) s += red[i];

    const float inv = 1.0f / s;
#pragma unroll
    for (int i = 0; i < 8; i++) p[t + i * 256] = tf32r(v[i] * inv);
}

// ---------------------------------------------------------------------------
// Launch pipeline (graph-capturable: kernels only)
// ---------------------------------------------------------------------------
extern "C" void kernel_launch(void* const* d_in, const int* in_sizes, int n_in,
                              void* d_out, int out_size)
{
    (void)in_sizes; (void)n_in; (void)out_size;
    const float* x  = (const float*)d_in[0];
    const float* Wq = (const float*)d_in[1];
    const float* bq = (const float*)d_in[2];
    const float* Wk = (const float*)d_in[3];
    const float* bk = (const float*)d_in[4];
    const float* Wv = (const float*)d_in[5];
    const float* bv = (const float*)d_in[6];
    float* out = (float*)d_out;

    float *q, *k, *v, *s, *xr, *wr;
    cudaGetSymbolAddress((void**)&q,  g_q);
    cudaGetSymbolAddress((void**)&k,  g_k);
    cudaGetSymbolAddress((void**)&v,  g_v);
    cudaGetSymbolAddress((void**)&s,  g_s);
    cudaGetSymbolAddress((void**)&xr, g_x);
    cudaGetSymbolAddress((void**)&wr, g_w);

    constexpr int SMEM_NT = 2 * (128 * 36 + 128 * 36) * 4;   // 73728
    constexpr int SMEM_NN = 2 * (128 * 36 + 32 * 136) * 4;   // 71680
    cudaFuncSetAttribute(gemm_tf32<true>,  cudaFuncAttributeMaxDynamicSharedMemorySize, SMEM_NT);
    cudaFuncSetAttribute(gemm_tf32<false>, cudaFuncAttributeMaxDynamicSharedMemorySize, SMEM_NN);

    const dim3 blk(128);

    // 0) pre-round x and W to tf32 so mma's truncation is exact
    {
        int n4x = BT_TOK * DMODEL / 4;
        round_tf32_kernel<<<(n4x + 255) / 256, 256>>>((const float4*)x, (float4*)xr, n4x);
        int n4w = DMODEL * DMODEL / 4;
        round_tf32_kernel<<<(n4w + 255) / 256, 256>>>((const float4*)Wq, (float4*)(wr + 0 * (size_t)DMODEL * DMODEL), n4w);
        round_tf32_kernel<<<(n4w + 255) / 256, 256>>>((const float4*)Wk, (float4*)(wr + 1 * (size_t)DMODEL * DMODEL), n4w);
        round_tf32_kernel<<<(n4w + 255) / 256, 256>>>((const float4*)Wv, (float4*)(wr + 2 * (size_t)DMODEL * DMODEL), n4w);
    }

    // 1) Q/K/V projections (outputs tf32-rounded), K-dim = DMODEL
    const dim3 g1(DMODEL / 128, BT_TOK / 128, 1);
    gemm_tf32<true><<<g1, blk, SMEM_NT>>>(xr, DMODEL, 0, wr + 0 * (size_t)DMODEL * DMODEL, DMODEL, 0,
                                          q, DMODEL, 0, bq, 1.0f, DMODEL, 1);
    gemm_tf32<true><<<g1, blk, SMEM_NT>>>(xr, DMODEL, 0, wr + 1 * (size_t)DMODEL * DMODEL, DMODEL, 0,
                                          k, DMODEL, 0, bk, 1.0f, DMODEL, 1);
    gemm_tf32<true><<<g1, blk, SMEM_NT>>>(xr, DMODEL, 0, wr + 2 * (size_t)DMODEL * DMODEL, DMODEL, 0,
                                          v, DMODEL, 0, bv, 1.0f, DMODEL, 1);

    // 2) S = Q K^T * scale per batch, K-dim = DMODEL
    const size_t sQKV = (size_t)TSEQ * DMODEL;
    const size_t sS   = (size_t)TSEQ * TSEQ;
    const dim3 g2(TSEQ / 128, TSEQ / 128, NBATCH);
    gemm_tf32<true><<<g2, blk, SMEM_NT>>>(q, DMODEL, sQKV, k, DMODEL, sQKV,
                                          s, TSEQ, sS, nullptr, SCALE, DMODEL, 0);

    // 3) softmax rows (writes tf32-rounded probabilities)
    softmax2048<<<NBATCH * TSEQ, 256>>>(s);

    // 4) O = P V per batch.  *** K-dim = TSEQ (2048), the R2 bug was here ***
    const dim3 g3(DMODEL / 128, TSEQ / 128, NBATCH);
    gemm_tf32<false><<<g3, blk, SMEM_NN>>>(s, TSEQ, sS, v, DMODEL, sQKV,
                                           out, DMODEL, sQKV, nullptr, 1.0f, TSEQ, 0);
}

// round 6
// speedup vs baseline: 1.9315x; 1.5119x over previous
#include <cuda_runtime.h>
#include <cuda_fp16.h>
#include <cstdint>
#include <cstddef>

// ---------------------------------------------------------------------------
// softmax(QK^T/32)V with Q/K/V = x W^T + b.
// fp16 mma.sync m16n8k16 (fp32 accum) pipeline; fp16 carries the same 10
// explicit mantissa bits as tf32 -> identical rounding error, 2x throughput.
// All GEMMs are NT (A[M,K]*B[N,K]^T); V produced transposed (Vt = Wv x^T).
// ---------------------------------------------------------------------------

#define BT_TOK   16384
#define DMODEL   1024
#define TSEQ     2048
#define NBATCH   8
#define SCALE    0.03125f

// Scratch (device globals; allocation forbidden)
__device__ __half g_qh[(size_t)BT_TOK * DMODEL];          // 32 MB
__device__ __half g_kh[(size_t)BT_TOK * DMODEL];          // 32 MB
__device__ __half g_vth[(size_t)DMODEL * BT_TOK];         // 32 MB  Vt[f, tok]
__device__ float  g_s[(size_t)NBATCH * TSEQ * TSEQ];      // 128 MB scores fp32
__device__ __half g_p[(size_t)NBATCH * TSEQ * TSEQ];      // 64 MB  probs half
__device__ __half g_xh[(size_t)BT_TOK * DMODEL];          // 32 MB
__device__ __half g_wh[3][(size_t)DMODEL * DMODEL];       // 6 MB

// ---------------- helpers ----------------
__device__ __forceinline__ unsigned smem_u32(const void* p) {
    unsigned a;
    asm("{ .reg .u64 t; cvta.to.shared.u64 t, %1; cvt.u32.u64 %0, t; }" : "=r"(a) : "l"(p));
    return a;
}
__device__ __forceinline__ void cp16(unsigned saddr, const void* g) {
    asm volatile("cp.async.cg.shared.global [%0], [%1], 16;" :: "r"(saddr), "l"(g));
}
__device__ __forceinline__ void cp_commit() { asm volatile("cp.async.commit_group;"); }
template <int N> __device__ __forceinline__ void cp_wait() {
    asm volatile("cp.async.wait_group %0;" :: "n"(N));
}
__device__ __forceinline__ void ldsm_x4(uint32_t r[4], unsigned addr) {
    asm volatile("ldmatrix.sync.aligned.m8n8.x4.shared.b16 {%0,%1,%2,%3}, [%4];"
                 : "=r"(r[0]), "=r"(r[1]), "=r"(r[2]), "=r"(r[3]) : "r"(addr));
}
__device__ __forceinline__ void mma_fp16(float c[4], const uint32_t a[4],
                                         uint32_t b0, uint32_t b1) {
    asm volatile(
        "mma.sync.aligned.m16n8k16.row.col.f32.f16.f16.f32 "
        "{%0,%1,%2,%3}, {%4,%5,%6,%7}, {%8,%9}, {%0,%1,%2,%3};"
        : "+f"(c[0]), "+f"(c[1]), "+f"(c[2]), "+f"(c[3])
        : "r"(a[0]), "r"(a[1]), "r"(a[2]), "r"(a[3]), "r"(b0), "r"(b1));
}

// ---------------------------------------------------------------------------
// NT fp16 GEMM: C[M,N] = alpha * A[M,K] * B[N,K]^T (+ bias)
// CTA tile 128x128, K-chunk 32, 128 threads (4 warps 2x2, warp tile 64x64).
// Smem: half rows, padded stride 40 halves (80 B) -> ldmatrix conflict-free.
// bias_mode: 0 none, 1 per-col (bias[n]), 2 per-row (bias[m]).  out_half: C dtype.
// ---------------------------------------------------------------------------
#define ROWB  80                         // bytes per smem row (40 halves)
#define STAGE (128 * ROWB)               // 10240 B per operand per buffer

__global__ void __launch_bounds__(128, 2)
gemm_fp16(const __half* __restrict__ A, int lda, size_t sA,
          const __half* __restrict__ B, int ldb, size_t sB,
          void* __restrict__ Cv, int ldc, size_t sC,
          const float* __restrict__ bias, int bias_mode,
          float alpha, int K, int out_half)
{
    __shared__ __align__(128) char smem[4 * STAGE];   // A0 A1 B0 B1
    const unsigned sb = smem_u32(smem);

    const int tid = threadIdx.x;
    const int lane = tid & 31;
    const int wid = tid >> 5;
    const int wm = (wid & 1) * 64;
    const int wn = (wid >> 1) * 64;

    A += blockIdx.z * sA;
    B += blockIdx.z * sB;
    const int m0 = blockIdx.y * 128;
    const int n0 = blockIdx.x * 128;

    // per-lane ldmatrix offset: matrix i = lane>>3 ({m0k0,m8k0,m0k8,m8k8}), row lane&7
    const int li = lane >> 3, lr = lane & 7;
    const unsigned offL = (unsigned)((((li & 1) * 8 + lr) * 40 + (li >> 1) * 8) * 2);

    // staging coords: 4 x 16B per thread per operand (128 rows x 64 B)
    const int srow = tid >> 2, scol = (tid & 3) * 8;     // scol in halves

    float acc[4][8][4] = {};

    auto load_stage = [&](int buf, int k0) {
        const __half* Ag = A + (size_t)m0 * lda + k0 + scol;
        const unsigned da = sb + buf * STAGE + scol * 2;
#pragma unroll
        for (int p = 0; p < 4; p++)
            cp16(da + (srow + p * 32) * ROWB, Ag + (size_t)(srow + p * 32) * lda);
        const __half* Bg = B + (size_t)n0 * ldb + k0 + scol;
        const unsigned db = sb + 2 * STAGE + buf * STAGE + scol * 2;
#pragma unroll
        for (int p = 0; p < 4; p++)
            cp16(db + (srow + p * 32) * ROWB, Bg + (size_t)(srow + p * 32) * ldb);
    };

    const int NK = K >> 5;
    load_stage(0, 0);
    cp_commit();

    for (int i = 0; i < NK; i++) {
        const int buf = i & 1;
        if (i + 1 < NK) {
            load_stage(buf ^ 1, (i + 1) * 32);
            cp_commit();
            cp_wait<1>();
        } else {
            cp_wait<0>();
        }
        __syncthreads();

        const unsigned Ab = sb + buf * STAGE + offL;
        const unsigned Bb = sb + 2 * STAGE + buf * STAGE + offL;

#pragma unroll
        for (int ks = 0; ks < 2; ks++) {
            uint32_t a[4][4];
#pragma unroll
            for (int mt = 0; mt < 4; mt++)
                ldsm_x4(a[mt], Ab + (wm + mt * 16) * ROWB + ks * 32);
            uint32_t bq[4][4];
#pragma unroll
            for (int g = 0; g < 4; g++)
                ldsm_x4(bq[g], Bb + (wn + g * 16) * ROWB + ks * 32);
#pragma unroll
            for (int mt = 0; mt < 4; mt++)
#pragma unroll
                for (int nt = 0; nt < 8; nt++) {
                    const int g = nt >> 1;
                    const uint32_t b0 = (nt & 1) ? bq[g][1] : bq[g][0];
                    const uint32_t b1 = (nt & 1) ? bq[g][3] : bq[g][2];
                    mma_fp16(acc[mt][nt], a[mt], b0, b1);
                }
        }
        __syncthreads();
    }

    // ---- epilogue (fragment layout: rows lane>>2 / +8, cols (lane&3)*2,+1) ----
    float* Cf = (float*)Cv + blockIdx.z * sC;
    __half* Ch = (__half*)Cv + blockIdx.z * sC;

#pragma unroll
    for (int nt = 0; nt < 8; nt++) {
        const int c = n0 + wn + nt * 8 + (lane & 3) * 2;
        float bx = 0.f, by = 0.f;
        if (bias_mode == 1) { bx = bias[c]; by = bias[c + 1]; }
#pragma unroll
        for (int mt = 0; mt < 4; mt++) {
            const int r = m0 + wm + mt * 16 + (lane >> 2);
            float r0x = acc[mt][nt][0] * alpha, r0y = acc[mt][nt][1] * alpha;
            float r1x = acc[mt][nt][2] * alpha, r1y = acc[mt][nt][3] * alpha;
            if (bias_mode == 1) { r0x += bx; r0y += by; r1x += bx; r1y += by; }
            else if (bias_mode == 2) {
                const float b0 = bias[r], b1 = bias[r + 8];
                r0x += b0; r0y += b0; r1x += b1; r1y += b1;
            }
            if (out_half) {
                *(__half2*)(Ch + (size_t)r * ldc + c)       = __floats2half2_rn(r0x, r0y);
                *(__half2*)(Ch + (size_t)(r + 8) * ldc + c) = __floats2half2_rn(r1x, r1y);
            } else {
                *(float2*)(Cf + (size_t)r * ldc + c)       = make_float2(r0x, r0y);
                *(float2*)(Cf + (size_t)(r + 8) * ldc + c) = make_float2(r1x, r1y);
            }
        }
    }
}

// ---------------------------------------------------------------------------
// fp32 -> fp16 conversion (rn), float4 -> 4 halves.
// ---------------------------------------------------------------------------
__global__ void __launch_bounds__(256)
f2h_kernel(const float4* __restrict__ in, __half2* __restrict__ out, int n4)
{
    int i = blockIdx.x * blockDim.x + threadIdx.x;
    if (i < n4) {
        float4 v = in[i];
        out[2 * i]     = __floats2half2_rn(v.x, v.y);
        out[2 * i + 1] = __floats2half2_rn(v.z, v.w);
    }
}

// ---------------------------------------------------------------------------
// Row softmax over 2048-wide fp32 rows -> fp16 probabilities.
// ---------------------------------------------------------------------------
__global__ void __launch_bounds__(256)
softmax2048(const float* __restrict__ S, __half* __restrict__ P)
{
    const int row = blockIdx.x;
    const float* p = S + (size_t)row * 2048;
    __half* o = P + (size_t)row * 2048;
    const int t = threadIdx.x;

    float v[8];
#pragma unroll
    for (int i = 0; i < 8; i++) v[i] = p[t + i * 256];

    float m = v[0];
#pragma unroll
    for (int i = 1; i < 8; i++) m = fmaxf(m, v[i]);
#pragma unroll
    for (int o2 = 16; o2; o2 >>= 1) m = fmaxf(m, __shfl_xor_sync(0xffffffffu, m, o2));

    __shared__ float red[8];
    if ((t & 31) == 0) red[t >> 5] = m;
    __syncthreads();
#pragma unroll
    for (int i = 0; i < 8; i++) m = fmaxf(m, red[i]);

    float s = 0.0f;
#pragma unroll
    for (int i = 0; i < 8; i++) { v[i] = __expf(v[i] - m); s += v[i]; }
#pragma unroll
    for (int o2 = 16; o2; o2 >>= 1) s += __shfl_xor_sync(0xffffffffu, s, o2);

    __syncthreads();
    if ((t & 31) == 0) red[t >> 5] = s;
    __syncthreads();
    s = 0.0f;
#pragma unroll
    for (int i = 0; i < 8; i++) s += red[i];

    const float inv = 1.0f / s;
#pragma unroll
    for (int i = 0; i < 8; i++) o[t + i * 256] = __float2half_rn(v[i] * inv);
}

// ---------------------------------------------------------------------------
// Launch pipeline (graph-capturable: kernels only)
// ---------------------------------------------------------------------------
extern "C" void kernel_launch(void* const* d_in, const int* in_sizes, int n_in,
                              void* d_out, int out_size)
{
    (void)in_sizes; (void)n_in; (void)out_size;
    const float* x  = (const float*)d_in[0];
    const float* Wq = (const float*)d_in[1];
    const float* bq = (const float*)d_in[2];
    const float* Wk = (const float*)d_in[3];
    const float* bk = (const float*)d_in[4];
    const float* Wv = (const float*)d_in[5];
    const float* bv = (const float*)d_in[6];
    float* out = (float*)d_out;

    __half *qh, *kh, *vth, *ph, *xh, *wh;
    float* s;
    cudaGetSymbolAddress((void**)&qh,  g_qh);
    cudaGetSymbolAddress((void**)&kh,  g_kh);
    cudaGetSymbolAddress((void**)&vth, g_vth);
    cudaGetSymbolAddress((void**)&s,   g_s);
    cudaGetSymbolAddress((void**)&ph,  g_p);
    cudaGetSymbolAddress((void**)&xh,  g_xh);
    cudaGetSymbolAddress((void**)&wh,  g_wh);

    const size_t WSZ = (size_t)DMODEL * DMODEL;

    // 0) convert inputs to fp16
    {
        int n4x = BT_TOK * DMODEL / 4;
        f2h_kernel<<<(n4x + 255) / 256, 256>>>((const float4*)x, (__half2*)xh, n4x);
        int n4w = DMODEL * DMODEL / 4;
        f2h_kernel<<<(n4w + 255) / 256, 256>>>((const float4*)Wq, (__half2*)(wh + 0 * WSZ), n4w);
        f2h_kernel<<<(n4w + 255) / 256, 256>>>((const float4*)Wk, (__half2*)(wh + 1 * WSZ), n4w);
        f2h_kernel<<<(n4w + 255) / 256, 256>>>((const float4*)Wv, (__half2*)(wh + 2 * WSZ), n4w);
    }

    const dim3 blk(128);
    const size_t sQK = (size_t)TSEQ * DMODEL;     // batch stride of Q/K (halves)
    const size_t sS  = (size_t)TSEQ * TSEQ;

    // 1) Q = x Wq^T + bq, K = x Wk^T + bk   [16384,1024] half out
    {
        dim3 g(DMODEL / 128, BT_TOK / 128, 1);
        gemm_fp16<<<g, blk>>>(xh, DMODEL, 0, wh + 0 * WSZ, DMODEL, 0,
                              qh, DMODEL, 0, bq, 1, 1.0f, DMODEL, 1);
        gemm_fp16<<<g, blk>>>(xh, DMODEL, 0, wh + 1 * WSZ, DMODEL, 0,
                              kh, DMODEL, 0, bk, 1, 1.0f, DMODEL, 1);
    }
    // 1b) Vt = Wv x^T + bv(per-row)   [1024, 16384] half out
    {
        dim3 g(BT_TOK / 128, DMODEL / 128, 1);
        gemm_fp16<<<g, blk>>>(wh + 2 * WSZ, DMODEL, 0, xh, DMODEL, 0,
                              vth, BT_TOK, 0, bv, 2, 1.0f, DMODEL, 1);
    }
    // 2) S = Q K^T * scale per batch   [2048,2048] fp32 out
    {
        dim3 g(TSEQ / 128, TSEQ / 128, NBATCH);
        gemm_fp16<<<g, blk>>>(qh, DMODEL, sQK, kh, DMODEL, sQK,
                              s, TSEQ, sS, nullptr, 0, SCALE, DMODEL, 0);
    }
    // 3) softmax rows -> fp16 P
    softmax2048<<<NBATCH * TSEQ, 256>>>(s, ph);

    // 4) O = P Vt^T per batch (fp32 out). B batch offset = z*2048 along k.
    {
        dim3 g(DMODEL / 128, TSEQ / 128, NBATCH);
        gemm_fp16<<<g, blk>>>(ph, TSEQ, sS, vth, BT_TOK, (size_t)TSEQ,
                              out, DMODEL, sQK, nullptr, 0, 1.0f, TSEQ, 0);
    }
}